// round 16
// baseline (speedup 1.0000x reference)
#include <cuda_runtime.h>
#include <cuda_fp16.h>

// Problem constants: N=100000, E=1600000, DIM=128, HEADS=8, HEAD_DIM=16
#define NMAX 100000
#define EMAX 1600000
#define LOG2E 1.4426950408889634f

static __device__ __half g_xh_h[NMAX * 128];   // projected features, fp16 [N,128]
static __device__ float  g_asrc[NMAX * 8];     // per-node src logits (pre-scaled by log2e)
static __device__ float  g_adst[NMAX * 8];     // per-node dst logits (pre-scaled by log2e)
static __device__ int    g_cnt[NMAX];          // in-degree
static __device__ int    g_off[NMAX];          // CSR offsets (block-local exclusive)
static __device__ int    g_bsum[128];          // per-1024-block sums -> exclusive prefix
static __device__ unsigned char g_epos8[EMAX]; // within-segment position (u8)
static __device__ int    g_csrc[EMAX];         // CSR: src per dst-sorted edge

__device__ __forceinline__ float lrelu(float s) { return (s > 0.f) ? s : 0.2f * s; }
__device__ __forceinline__ float ex2(float x) {
    float r;
    asm("ex2.approx.f32 %0, %1;" : "=f"(r) : "f"(x));
    return r;
}

#define LDSM4(r0, r1, r2, r3, addr)                                           \
    asm volatile("ldmatrix.sync.aligned.m8n8.x4.shared.b16 {%0,%1,%2,%3}, [%4];" \
                 : "=r"(r0), "=r"(r1), "=r"(r2), "=r"(r3) : "r"(addr))

#define MMA16816(d, a0, a1, a2, a3, b0, b1)                                   \
    asm volatile("mma.sync.aligned.m16n8k16.row.col.f32.f16.f16.f32 "         \
                 "{%0,%1,%2,%3}, {%4,%5,%6,%7}, {%8,%9}, {%0,%1,%2,%3};"      \
                 : "+f"(d[0]), "+f"(d[1]), "+f"(d[2]), "+f"(d[3])             \
                 : "r"(a0), "r"(a1), "r"(a2), "r"(a3), "r"(b0), "r"(b1))

// ---------------------------------------------------------------------------
// Tensor-core GEMM: xh = x @ W^T + b_proj, full 128-col tile per CTA.
// W split hi+residual fp16 pair. Epilogue: fp16 xh + log2e-scaled logits.
// ---------------------------------------------------------------------------
__global__ __launch_bounds__(256) void gemm_tc(const float* __restrict__ x,
                                               const float* __restrict__ W,
                                               const float* __restrict__ b,
                                               const float* __restrict__ att_s,
                                               const float* __restrict__ att_d,
                                               int n) {
    extern __shared__ __half sm[];
    __half* xs = sm;                  // [128][136]
    __half* wh = sm + 128 * 136;      // [128][136]
    __half* wl = wh + 128 * 136;      // [128][136]

    const int t = threadIdx.x;
    const int row0 = blockIdx.x * 128;

#pragma unroll
    for (int i = 0; i < 16; i++) {
        int idx = t + i * 256;
        int r = idx >> 5, kq = idx & 31;
        float4 v = make_float4(0.f, 0.f, 0.f, 0.f);
        if (row0 + r < n)
            v = *reinterpret_cast<const float4*>(&x[(row0 + r) * 128 + kq * 4]);
        union { __half2 h2[2]; uint2 u; } pk;
        pk.h2[0] = __floats2half2_rn(v.x, v.y);
        pk.h2[1] = __floats2half2_rn(v.z, v.w);
        *reinterpret_cast<uint2*>(&xs[r * 136 + kq * 4]) = pk.u;
    }
#pragma unroll
    for (int i = 0; i < 16; i++) {
        int idx = t + i * 256;
        int r = idx >> 5, kq = idx & 31;
        float4 v = *reinterpret_cast<const float4*>(&W[r * 128 + kq * 4]);
        __half hx = __float2half_rn(v.x), hy = __float2half_rn(v.y);
        __half hz = __float2half_rn(v.z), hw = __float2half_rn(v.w);
        union { __half2 h2[2]; uint2 u; } ph, pl;
        ph.h2[0] = __halves2half2(hx, hy);
        ph.h2[1] = __halves2half2(hz, hw);
        pl.h2[0] = __floats2half2_rn(v.x - __half2float(hx), v.y - __half2float(hy));
        pl.h2[1] = __floats2half2_rn(v.z - __half2float(hz), v.w - __half2float(hw));
        *reinterpret_cast<uint2*>(&wh[r * 136 + kq * 4]) = ph.u;
        *reinterpret_cast<uint2*>(&wl[r * 136 + kq * 4]) = pl.u;
    }
    __syncthreads();

    const int lane = t & 31, wid = t >> 5;
    const int wm0 = (wid & 3) * 32;
    const int wn0 = (wid >> 2) * 64;

    const unsigned xsA = (unsigned)__cvta_generic_to_shared(xs);
    const unsigned whA = (unsigned)__cvta_generic_to_shared(wh);
    const unsigned wlA = (unsigned)__cvta_generic_to_shared(wl);

    const int arow = lane & 15;
    const int acol = (lane >> 4) * 8;
    const int bnof = (lane & 7) + ((lane >> 1) & 8);
    const int bkof = ((lane >> 3) & 1) * 8;

    float acc[2][8][4];
#pragma unroll
    for (int mt = 0; mt < 2; mt++)
#pragma unroll
        for (int nt = 0; nt < 8; nt++)
#pragma unroll
            for (int r = 0; r < 4; r++) acc[mt][nt][r] = 0.f;

#pragma unroll
    for (int kk = 0; kk < 8; kk++) {
        const int k0 = kk * 16;
        unsigned a[2][4];
#pragma unroll
        for (int mt = 0; mt < 2; mt++) {
            unsigned addr = xsA + ((wm0 + mt * 16 + arow) * 136 + k0 + acol) * 2;
            LDSM4(a[mt][0], a[mt][1], a[mt][2], a[mt][3], addr);
        }
#pragma unroll
        for (int ng = 0; ng < 4; ng++) {
            unsigned bh[4], bl[4];
            unsigned off = ((wn0 + ng * 16 + bnof) * 136 + k0 + bkof) * 2;
            LDSM4(bh[0], bh[1], bh[2], bh[3], whA + off);
            LDSM4(bl[0], bl[1], bl[2], bl[3], wlA + off);
#pragma unroll
            for (int mt = 0; mt < 2; mt++)
#pragma unroll
                for (int sub = 0; sub < 2; sub++) {
                    MMA16816(acc[mt][ng * 2 + sub], a[mt][0], a[mt][1], a[mt][2], a[mt][3],
                             bh[sub * 2], bh[sub * 2 + 1]);
                    MMA16816(acc[mt][ng * 2 + sub], a[mt][0], a[mt][1], a[mt][2], a[mt][3],
                             bl[sub * 2], bl[sub * 2 + 1]);
                }
        }
    }

    __syncthreads();
    __half* S = xs;                    // [128][136] reuse
#pragma unroll
    for (int mt = 0; mt < 2; mt++)
#pragma unroll
        for (int nt = 0; nt < 8; nt++) {
            int r = wm0 + mt * 16 + (lane >> 2);
            int c = wn0 + nt * 8 + (lane & 3) * 2;
            float bc0 = __ldg(&b[c]), bc1 = __ldg(&b[c + 1]);
            *reinterpret_cast<__half2*>(&S[r * 136 + c]) =
                __floats2half2_rn(acc[mt][nt][0] + bc0, acc[mt][nt][1] + bc1);
            *reinterpret_cast<__half2*>(&S[(r + 8) * 136 + c]) =
                __floats2half2_rn(acc[mt][nt][2] + bc0, acc[mt][nt][3] + bc1);
        }
    __syncthreads();

    {
        int row = t >> 1, hh = t & 1;
        int grow = row0 + row;
        if (grow < n) {
            int c0 = hh * 64;
            float sd[4] = {0.f, 0.f, 0.f, 0.f}, dd[4] = {0.f, 0.f, 0.f, 0.f};
#pragma unroll
            for (int q = 0; q < 8; q++) {
                uint4 u = *reinterpret_cast<uint4*>(&S[row * 136 + c0 + q * 8]);
                *reinterpret_cast<uint4*>(&g_xh_h[grow * 128 + c0 + q * 8]) = u;
                int hs = q >> 1;
                const unsigned* uw = reinterpret_cast<const unsigned*>(&u);
#pragma unroll
                for (int p = 0; p < 4; p++) {
                    float2 f = __half22float2(*reinterpret_cast<const __half2*>(&uw[p]));
                    int gc = c0 + q * 8 + p * 2;
                    sd[hs] += f.x * __ldg(&att_s[gc]) + f.y * __ldg(&att_s[gc + 1]);
                    dd[hs] += f.x * __ldg(&att_d[gc]) + f.y * __ldg(&att_d[gc + 1]);
                }
            }
            float4 so = {sd[0] * LOG2E, sd[1] * LOG2E, sd[2] * LOG2E, sd[3] * LOG2E};
            float4 doo = {dd[0] * LOG2E, dd[1] * LOG2E, dd[2] * LOG2E, dd[3] * LOG2E};
            *reinterpret_cast<float4*>(&g_asrc[grow * 8 + hh * 4]) = so;
            *reinterpret_cast<float4*>(&g_adst[grow * 8 + hh * 4]) = doo;
        }
    }
}

// ---------------------------------------------------------------------------
// CSR construction: memset(cnt) -> hist -> scan1 -> tiny bsum-scan; fill runs
// later on the main stream with the whole machine.
// ---------------------------------------------------------------------------
__global__ __launch_bounds__(256) void hist_kernel(const int* __restrict__ ei, int E) {
    int e = blockIdx.x * 256 + threadIdx.x;
    if (e < E) g_epos8[e] = (unsigned char)atomicAdd(&g_cnt[ei[E + e]], 1);
}

__global__ __launch_bounds__(256) void scan1_kernel(int n) {
    __shared__ int s[256];
    int b = blockIdx.x, t = threadIdx.x;
    int base = b * 1024 + t * 4;
    int v[4];
#pragma unroll
    for (int j = 0; j < 4; j++) v[j] = (base + j < n) ? g_cnt[base + j] : 0;
    int local = v[0] + v[1] + v[2] + v[3];
    s[t] = local;
    __syncthreads();
    for (int off = 1; off < 256; off <<= 1) {
        int xv = (t >= off) ? s[t - off] : 0;
        __syncthreads();
        s[t] += xv;
        __syncthreads();
    }
    int run = s[t] - local;
#pragma unroll
    for (int j = 0; j < 4; j++) {
        if (base + j < n) g_off[base + j] = run;
        run += v[j];
    }
    if (t == 255) g_bsum[b] = s[255];
}

// tiny: 1 block, exclusive-scan the <=128 block sums in place
__global__ __launch_bounds__(128) void scan2_kernel(int nb) {
    __shared__ int s[128];
    int t = threadIdx.x;
    int v = (t < nb) ? g_bsum[t] : 0;
    s[t] = v;
    __syncthreads();
    for (int off = 1; off < 128; off <<= 1) {
        int xv = (t >= off) ? s[t - off] : 0;
        __syncthreads();
        s[t] += xv;
        __syncthreads();
    }
    if (t < nb) g_bsum[t] = s[t] - v;   // exclusive prefix
}

__global__ __launch_bounds__(256) void fill_kernel(const int* __restrict__ ei, int E) {
    int e = blockIdx.x * 256 + threadIdx.x;
    if (e >= E) return;
    int dst = ei[E + e];
    int base = g_off[dst] + __ldg(&g_bsum[dst >> 10]);
    g_csrc[base + (int)g_epos8[e]] = ei[e];
}

// ---------------------------------------------------------------------------
// Fused gather (measured-best layout): 2 warps/CTA, one node per warp;
// per-lane csrc prefetch + shfl distribution; single-MUFU ex2 weights.
// ---------------------------------------------------------------------------
__global__ __launch_bounds__(64) void gather_kernel(const float* __restrict__ bias,
                                                    float* __restrict__ out, int n) {
    int node = blockIdx.x * 2 + (threadIdx.x >> 5);
    int lane = threadIdx.x & 31;
    if (node >= n) return;
    const uint2* xh2 = reinterpret_cast<const uint2*>(g_xh_h);
    const int hoff = lane >> 2;

    float ad = __ldg(&g_adst[node * 8 + hoff]);
    float ex = ex2(lrelu(__ldg(&g_asrc[node * 8 + hoff]) + ad));
    float dsum = ex;

    uint2 sv = __ldg(&xh2[node * 32 + lane]);
    float2 f0 = __half22float2(*reinterpret_cast<__half2*>(&sv.x));
    float2 f1 = __half22float2(*reinterpret_cast<__half2*>(&sv.y));
    float4 acc = {ex * f0.x, ex * f0.y, ex * f1.x, ex * f1.y};

    const int beg = __ldg(&g_off[node]) + __ldg(&g_bsum[node >> 10]);
    const int cnt = __ldg(&g_cnt[node]);

    for (int c0 = 0; c0 < cnt; c0 += 32) {
        const int rem = min(cnt - c0, 32);
        int myidx = (lane < rem) ? __ldg(&g_csrc[beg + c0 + lane]) : 0;

        int j = 0;
        for (; j + 4 <= rem; j += 4) {
            int sA = __shfl_sync(0xffffffffu, myidx, j);
            int sB = __shfl_sync(0xffffffffu, myidx, j + 1);
            int sC = __shfl_sync(0xffffffffu, myidx, j + 2);
            int sD = __shfl_sync(0xffffffffu, myidx, j + 3);
            float aA = __ldg(&g_asrc[sA * 8 + hoff]);
            float aB = __ldg(&g_asrc[sB * 8 + hoff]);
            float aC = __ldg(&g_asrc[sC * 8 + hoff]);
            float aD = __ldg(&g_asrc[sD * 8 + hoff]);
            uint2 vA = __ldg(&xh2[sA * 32 + lane]);
            uint2 vB = __ldg(&xh2[sB * 32 + lane]);
            uint2 vC = __ldg(&xh2[sC * 32 + lane]);
            uint2 vD = __ldg(&xh2[sD * 32 + lane]);
            float eA = ex2(lrelu(aA + ad));
            float eB = ex2(lrelu(aB + ad));
            float eC = ex2(lrelu(aC + ad));
            float eD = ex2(lrelu(aD + ad));
            dsum += eA + eB + eC + eD;
            float2 a0 = __half22float2(*reinterpret_cast<__half2*>(&vA.x));
            float2 a1 = __half22float2(*reinterpret_cast<__half2*>(&vA.y));
            float2 b0 = __half22float2(*reinterpret_cast<__half2*>(&vB.x));
            float2 b1 = __half22float2(*reinterpret_cast<__half2*>(&vB.y));
            float2 c4 = __half22float2(*reinterpret_cast<__half2*>(&vC.x));
            float2 c1 = __half22float2(*reinterpret_cast<__half2*>(&vC.y));
            float2 d0 = __half22float2(*reinterpret_cast<__half2*>(&vD.x));
            float2 d1 = __half22float2(*reinterpret_cast<__half2*>(&vD.y));
            acc.x += eA * a0.x + eB * b0.x + eC * c4.x + eD * d0.x;
            acc.y += eA * a0.y + eB * b0.y + eC * c4.y + eD * d0.y;
            acc.z += eA * a1.x + eB * b1.x + eC * c1.x + eD * d1.x;
            acc.w += eA * a1.y + eB * b1.y + eC * c1.y + eD * d1.y;
        }
        for (; j < rem; j++) {
            int s = __shfl_sync(0xffffffffu, myidx, j);
            float e = ex2(lrelu(__ldg(&g_asrc[s * 8 + hoff]) + ad));
            dsum += e;
            uint2 v = __ldg(&xh2[s * 32 + lane]);
            float2 p0 = __half22float2(*reinterpret_cast<__half2*>(&v.x));
            float2 p1 = __half22float2(*reinterpret_cast<__half2*>(&v.y));
            acc.x += e * p0.x; acc.y += e * p0.y; acc.z += e * p1.x; acc.w += e * p1.y;
        }
    }

    float inv = 1.0f / dsum;
    float4 bv = __ldg(&reinterpret_cast<const float4*>(bias)[lane]);
    float4 o = {acc.x * inv + bv.x, acc.y * inv + bv.y,
                acc.z * inv + bv.z, acc.w * inv + bv.w};
    reinterpret_cast<float4*>(out)[node * 32 + lane] = o;
}

// ---------------------------------------------------------------------------
extern "C" void kernel_launch(void* const* d_in, const int* in_sizes, int n_in,
                              void* d_out, int out_size) {
    const float* x     = (const float*)d_in[0];
    const int*   ei    = (const int*)  d_in[1];
    const float* W     = (const float*)d_in[2];
    const float* bproj = (const float*)d_in[3];
    const float* att_s = (const float*)d_in[4];
    const float* att_d = (const float*)d_in[5];
    const float* bias  = (const float*)d_in[6];
    float* out = (float*)d_out;

    const int n = in_sizes[0] / 128;
    const int E = in_sizes[1] / 2;
    const int nb = (n + 1023) >> 10;
    const int smem_bytes = 3 * 128 * 136 * 2;   // 104448

    static cudaStream_t s_csr = nullptr;
    static cudaEvent_t ev_fork = nullptr, ev_join = nullptr;
    static void* p_cnt = nullptr;
    if (!s_csr) {
        cudaStreamCreateWithFlags(&s_csr, cudaStreamNonBlocking);
        cudaEventCreateWithFlags(&ev_fork, cudaEventDisableTiming);
        cudaEventCreateWithFlags(&ev_join, cudaEventDisableTiming);
        cudaFuncSetAttribute(gemm_tc, cudaFuncAttributeMaxDynamicSharedMemorySize,
                             smem_bytes);
        cudaGetSymbolAddress(&p_cnt, g_cnt);
    }

    // Parallel section: hist+scan (~24us of work) balanced against gemm (~25us).
    cudaEventRecord(ev_fork, 0);
    cudaStreamWaitEvent(s_csr, ev_fork, 0);
    cudaMemsetAsync(p_cnt, 0, (size_t)n * sizeof(int), s_csr);
    hist_kernel<<<(E + 255) / 256, 256, 0, s_csr>>>(ei, E);
    scan1_kernel<<<nb, 256, 0, s_csr>>>(n);
    scan2_kernel<<<1, 128, 0, s_csr>>>(nb);
    cudaEventRecord(ev_join, s_csr);

    gemm_tc<<<(n + 127) / 128, 256, smem_bytes>>>(x, W, bproj, att_s, att_d, n);

    // fill runs alone on the full machine (after gemm AND the scan chain).
    cudaStreamWaitEvent(0, ev_join, 0);
    fill_kernel<<<(E + 255) / 256, 256>>>(ei, E);
    gather_kernel<<<(n + 1) / 2, 64>>>(bias, out, n);
}

// round 17
// speedup vs baseline: 1.0835x; 1.0835x over previous
#include <cuda_runtime.h>
#include <cuda_fp16.h>

// Problem constants: N=100000, E=1600000, DIM=128, HEADS=8, HEAD_DIM=16
#define NMAX 100000
#define EMAX 1600000
#define LOG2E 1.4426950408889634f

static __device__ __half g_xh_h[NMAX * 128];   // projected features, fp16 [N,128]
static __device__ float  g_asrc[NMAX * 8];     // per-node src logits (pre-scaled by log2e)
static __device__ float  g_adst[NMAX * 8];     // per-node dst logits (pre-scaled by log2e)
static __device__ int    g_cnt[NMAX];          // in-degree
static __device__ int    g_off[NMAX];          // CSR offsets (block-local exclusive)
static __device__ int    g_bsum[128];          // per-1024-block sums -> exclusive prefix
static __device__ unsigned char g_epos8[EMAX]; // within-segment position (u8)
static __device__ int    g_csrc[EMAX];         // CSR: src per dst-sorted edge

__device__ __forceinline__ float lrelu(float s) { return (s > 0.f) ? s : 0.2f * s; }
__device__ __forceinline__ float ex2(float x) {
    float r;
    asm("ex2.approx.f32 %0, %1;" : "=f"(r) : "f"(x));
    return r;
}

#define LDSM4(r0, r1, r2, r3, addr)                                           \
    asm volatile("ldmatrix.sync.aligned.m8n8.x4.shared.b16 {%0,%1,%2,%3}, [%4];" \
                 : "=r"(r0), "=r"(r1), "=r"(r2), "=r"(r3) : "r"(addr))

#define MMA16816(d, a0, a1, a2, a3, b0, b1)                                   \
    asm volatile("mma.sync.aligned.m16n8k16.row.col.f32.f16.f16.f32 "         \
                 "{%0,%1,%2,%3}, {%4,%5,%6,%7}, {%8,%9}, {%0,%1,%2,%3};"      \
                 : "+f"(d[0]), "+f"(d[1]), "+f"(d[2]), "+f"(d[3])             \
                 : "r"(a0), "r"(a1), "r"(a2), "r"(a3), "r"(b0), "r"(b1))

// ---------------------------------------------------------------------------
// Tensor-core GEMM: xh = x @ W^T + b_proj, full 128-col tile per CTA.
// W plain fp16 (residual dropped: error budget allows ~4.8e-4 total).
// Epilogue: fp16 xh + log2e-scaled logits. SMEM: xs + wh = 69632 B.
// ---------------------------------------------------------------------------
__global__ __launch_bounds__(256) void gemm_tc(const float* __restrict__ x,
                                               const float* __restrict__ W,
                                               const float* __restrict__ b,
                                               const float* __restrict__ att_s,
                                               const float* __restrict__ att_d,
                                               int n) {
    extern __shared__ __half sm[];
    __half* xs = sm;                  // [128][136]
    __half* wh = sm + 128 * 136;      // [128][136]

    const int t = threadIdx.x;
    const int row0 = blockIdx.x * 128;

#pragma unroll
    for (int i = 0; i < 16; i++) {
        int idx = t + i * 256;
        int r = idx >> 5, kq = idx & 31;
        float4 v = make_float4(0.f, 0.f, 0.f, 0.f);
        if (row0 + r < n)
            v = *reinterpret_cast<const float4*>(&x[(row0 + r) * 128 + kq * 4]);
        union { __half2 h2[2]; uint2 u; } pk;
        pk.h2[0] = __floats2half2_rn(v.x, v.y);
        pk.h2[1] = __floats2half2_rn(v.z, v.w);
        *reinterpret_cast<uint2*>(&xs[r * 136 + kq * 4]) = pk.u;
    }
#pragma unroll
    for (int i = 0; i < 16; i++) {
        int idx = t + i * 256;
        int r = idx >> 5, kq = idx & 31;
        float4 v = *reinterpret_cast<const float4*>(&W[r * 128 + kq * 4]);
        union { __half2 h2[2]; uint2 u; } ph;
        ph.h2[0] = __floats2half2_rn(v.x, v.y);
        ph.h2[1] = __floats2half2_rn(v.z, v.w);
        *reinterpret_cast<uint2*>(&wh[r * 136 + kq * 4]) = ph.u;
    }
    __syncthreads();

    const int lane = t & 31, wid = t >> 5;
    const int wm0 = (wid & 3) * 32;
    const int wn0 = (wid >> 2) * 64;

    const unsigned xsA = (unsigned)__cvta_generic_to_shared(xs);
    const unsigned whA = (unsigned)__cvta_generic_to_shared(wh);

    const int arow = lane & 15;
    const int acol = (lane >> 4) * 8;
    const int bnof = (lane & 7) + ((lane >> 1) & 8);
    const int bkof = ((lane >> 3) & 1) * 8;

    float acc[2][8][4];
#pragma unroll
    for (int mt = 0; mt < 2; mt++)
#pragma unroll
        for (int nt = 0; nt < 8; nt++)
#pragma unroll
            for (int r = 0; r < 4; r++) acc[mt][nt][r] = 0.f;

#pragma unroll
    for (int kk = 0; kk < 8; kk++) {
        const int k0 = kk * 16;
        unsigned a[2][4];
#pragma unroll
        for (int mt = 0; mt < 2; mt++) {
            unsigned addr = xsA + ((wm0 + mt * 16 + arow) * 136 + k0 + acol) * 2;
            LDSM4(a[mt][0], a[mt][1], a[mt][2], a[mt][3], addr);
        }
#pragma unroll
        for (int ng = 0; ng < 4; ng++) {
            unsigned bh[4];
            unsigned off = ((wn0 + ng * 16 + bnof) * 136 + k0 + bkof) * 2;
            LDSM4(bh[0], bh[1], bh[2], bh[3], whA + off);
#pragma unroll
            for (int mt = 0; mt < 2; mt++)
#pragma unroll
                for (int sub = 0; sub < 2; sub++) {
                    MMA16816(acc[mt][ng * 2 + sub], a[mt][0], a[mt][1], a[mt][2], a[mt][3],
                             bh[sub * 2], bh[sub * 2 + 1]);
                }
        }
    }

    __syncthreads();
    __half* S = xs;                    // [128][136] reuse
#pragma unroll
    for (int mt = 0; mt < 2; mt++)
#pragma unroll
        for (int nt = 0; nt < 8; nt++) {
            int r = wm0 + mt * 16 + (lane >> 2);
            int c = wn0 + nt * 8 + (lane & 3) * 2;
            float bc0 = __ldg(&b[c]), bc1 = __ldg(&b[c + 1]);
            *reinterpret_cast<__half2*>(&S[r * 136 + c]) =
                __floats2half2_rn(acc[mt][nt][0] + bc0, acc[mt][nt][1] + bc1);
            *reinterpret_cast<__half2*>(&S[(r + 8) * 136 + c]) =
                __floats2half2_rn(acc[mt][nt][2] + bc0, acc[mt][nt][3] + bc1);
        }
    __syncthreads();

    {
        int row = t >> 1, hh = t & 1;
        int grow = row0 + row;
        if (grow < n) {
            int c0 = hh * 64;
            float sd[4] = {0.f, 0.f, 0.f, 0.f}, dd[4] = {0.f, 0.f, 0.f, 0.f};
#pragma unroll
            for (int q = 0; q < 8; q++) {
                uint4 u = *reinterpret_cast<uint4*>(&S[row * 136 + c0 + q * 8]);
                *reinterpret_cast<uint4*>(&g_xh_h[grow * 128 + c0 + q * 8]) = u;
                int hs = q >> 1;
                const unsigned* uw = reinterpret_cast<const unsigned*>(&u);
#pragma unroll
                for (int p = 0; p < 4; p++) {
                    float2 f = __half22float2(*reinterpret_cast<const __half2*>(&uw[p]));
                    int gc = c0 + q * 8 + p * 2;
                    sd[hs] += f.x * __ldg(&att_s[gc]) + f.y * __ldg(&att_s[gc + 1]);
                    dd[hs] += f.x * __ldg(&att_d[gc]) + f.y * __ldg(&att_d[gc + 1]);
                }
            }
            float4 so = {sd[0] * LOG2E, sd[1] * LOG2E, sd[2] * LOG2E, sd[3] * LOG2E};
            float4 doo = {dd[0] * LOG2E, dd[1] * LOG2E, dd[2] * LOG2E, dd[3] * LOG2E};
            *reinterpret_cast<float4*>(&g_asrc[grow * 8 + hh * 4]) = so;
            *reinterpret_cast<float4*>(&g_adst[grow * 8 + hh * 4]) = doo;
        }
    }
}

// ---------------------------------------------------------------------------
// CSR construction: memset(cnt) -> hist -> scan1 -> tiny bsum-scan; fill runs
// later on the main stream with the whole machine.
// ---------------------------------------------------------------------------
__global__ __launch_bounds__(256) void hist_kernel(const int* __restrict__ ei, int E) {
    int e = blockIdx.x * 256 + threadIdx.x;
    if (e < E) g_epos8[e] = (unsigned char)atomicAdd(&g_cnt[ei[E + e]], 1);
}

__global__ __launch_bounds__(256) void scan1_kernel(int n) {
    __shared__ int s[256];
    int b = blockIdx.x, t = threadIdx.x;
    int base = b * 1024 + t * 4;
    int v[4];
#pragma unroll
    for (int j = 0; j < 4; j++) v[j] = (base + j < n) ? g_cnt[base + j] : 0;
    int local = v[0] + v[1] + v[2] + v[3];
    s[t] = local;
    __syncthreads();
    for (int off = 1; off < 256; off <<= 1) {
        int xv = (t >= off) ? s[t - off] : 0;
        __syncthreads();
        s[t] += xv;
        __syncthreads();
    }
    int run = s[t] - local;
#pragma unroll
    for (int j = 0; j < 4; j++) {
        if (base + j < n) g_off[base + j] = run;
        run += v[j];
    }
    if (t == 255) g_bsum[b] = s[255];
}

// tiny: 1 block, exclusive-scan the <=128 block sums in place
__global__ __launch_bounds__(128) void scan2_kernel(int nb) {
    __shared__ int s[128];
    int t = threadIdx.x;
    int v = (t < nb) ? g_bsum[t] : 0;
    s[t] = v;
    __syncthreads();
    for (int off = 1; off < 128; off <<= 1) {
        int xv = (t >= off) ? s[t - off] : 0;
        __syncthreads();
        s[t] += xv;
        __syncthreads();
    }
    if (t < nb) g_bsum[t] = s[t] - v;   // exclusive prefix
}

__global__ __launch_bounds__(256) void fill_kernel(const int* __restrict__ ei, int E) {
    int e = blockIdx.x * 256 + threadIdx.x;
    if (e >= E) return;
    int dst = ei[E + e];
    int base = g_off[dst] + __ldg(&g_bsum[dst >> 10]);
    g_csrc[base + (int)g_epos8[e]] = ei[e];
}

// ---------------------------------------------------------------------------
// Fused gather (measured-best layout): 2 warps/CTA, one node per warp;
// per-lane csrc prefetch + shfl distribution; single-MUFU ex2 weights.
// ---------------------------------------------------------------------------
__global__ __launch_bounds__(64) void gather_kernel(const float* __restrict__ bias,
                                                    float* __restrict__ out, int n) {
    int node = blockIdx.x * 2 + (threadIdx.x >> 5);
    int lane = threadIdx.x & 31;
    if (node >= n) return;
    const uint2* xh2 = reinterpret_cast<const uint2*>(g_xh_h);
    const int hoff = lane >> 2;

    float ad = __ldg(&g_adst[node * 8 + hoff]);
    float ex = ex2(lrelu(__ldg(&g_asrc[node * 8 + hoff]) + ad));
    float dsum = ex;

    uint2 sv = __ldg(&xh2[node * 32 + lane]);
    float2 f0 = __half22float2(*reinterpret_cast<__half2*>(&sv.x));
    float2 f1 = __half22float2(*reinterpret_cast<__half2*>(&sv.y));
    float4 acc = {ex * f0.x, ex * f0.y, ex * f1.x, ex * f1.y};

    const int beg = __ldg(&g_off[node]) + __ldg(&g_bsum[node >> 10]);
    const int cnt = __ldg(&g_cnt[node]);

    for (int c0 = 0; c0 < cnt; c0 += 32) {
        const int rem = min(cnt - c0, 32);
        int myidx = (lane < rem) ? __ldg(&g_csrc[beg + c0 + lane]) : 0;

        int j = 0;
        for (; j + 4 <= rem; j += 4) {
            int sA = __shfl_sync(0xffffffffu, myidx, j);
            int sB = __shfl_sync(0xffffffffu, myidx, j + 1);
            int sC = __shfl_sync(0xffffffffu, myidx, j + 2);
            int sD = __shfl_sync(0xffffffffu, myidx, j + 3);
            float aA = __ldg(&g_asrc[sA * 8 + hoff]);
            float aB = __ldg(&g_asrc[sB * 8 + hoff]);
            float aC = __ldg(&g_asrc[sC * 8 + hoff]);
            float aD = __ldg(&g_asrc[sD * 8 + hoff]);
            uint2 vA = __ldg(&xh2[sA * 32 + lane]);
            uint2 vB = __ldg(&xh2[sB * 32 + lane]);
            uint2 vC = __ldg(&xh2[sC * 32 + lane]);
            uint2 vD = __ldg(&xh2[sD * 32 + lane]);
            float eA = ex2(lrelu(aA + ad));
            float eB = ex2(lrelu(aB + ad));
            float eC = ex2(lrelu(aC + ad));
            float eD = ex2(lrelu(aD + ad));
            dsum += eA + eB + eC + eD;
            float2 a0 = __half22float2(*reinterpret_cast<__half2*>(&vA.x));
            float2 a1 = __half22float2(*reinterpret_cast<__half2*>(&vA.y));
            float2 b0 = __half22float2(*reinterpret_cast<__half2*>(&vB.x));
            float2 b1 = __half22float2(*reinterpret_cast<__half2*>(&vB.y));
            float2 c4 = __half22float2(*reinterpret_cast<__half2*>(&vC.x));
            float2 c1 = __half22float2(*reinterpret_cast<__half2*>(&vC.y));
            float2 d0 = __half22float2(*reinterpret_cast<__half2*>(&vD.x));
            float2 d1 = __half22float2(*reinterpret_cast<__half2*>(&vD.y));
            acc.x += eA * a0.x + eB * b0.x + eC * c4.x + eD * d0.x;
            acc.y += eA * a0.y + eB * b0.y + eC * c4.y + eD * d0.y;
            acc.z += eA * a1.x + eB * b1.x + eC * c1.x + eD * d1.x;
            acc.w += eA * a1.y + eB * b1.y + eC * c1.y + eD * d1.y;
        }
        for (; j < rem; j++) {
            int s = __shfl_sync(0xffffffffu, myidx, j);
            float e = ex2(lrelu(__ldg(&g_asrc[s * 8 + hoff]) + ad));
            dsum += e;
            uint2 v = __ldg(&xh2[s * 32 + lane]);
            float2 p0 = __half22float2(*reinterpret_cast<__half2*>(&v.x));
            float2 p1 = __half22float2(*reinterpret_cast<__half2*>(&v.y));
            acc.x += e * p0.x; acc.y += e * p0.y; acc.z += e * p1.x; acc.w += e * p1.y;
        }
    }

    float inv = 1.0f / dsum;
    float4 bv = __ldg(&reinterpret_cast<const float4*>(bias)[lane]);
    float4 o = {acc.x * inv + bv.x, acc.y * inv + bv.y,
                acc.z * inv + bv.z, acc.w * inv + bv.w};
    reinterpret_cast<float4*>(out)[node * 32 + lane] = o;
}

// ---------------------------------------------------------------------------
extern "C" void kernel_launch(void* const* d_in, const int* in_sizes, int n_in,
                              void* d_out, int out_size) {
    const float* x     = (const float*)d_in[0];
    const int*   ei    = (const int*)  d_in[1];
    const float* W     = (const float*)d_in[2];
    const float* bproj = (const float*)d_in[3];
    const float* att_s = (const float*)d_in[4];
    const float* att_d = (const float*)d_in[5];
    const float* bias  = (const float*)d_in[6];
    float* out = (float*)d_out;

    const int n = in_sizes[0] / 128;
    const int E = in_sizes[1] / 2;
    const int nb = (n + 1023) >> 10;
    const int smem_bytes = 2 * 128 * 136 * 2;   // 69632

    static cudaStream_t s_csr = nullptr;
    static cudaEvent_t ev_fork = nullptr, ev_join = nullptr;
    static void* p_cnt = nullptr;
    if (!s_csr) {
        cudaStreamCreateWithFlags(&s_csr, cudaStreamNonBlocking);
        cudaEventCreateWithFlags(&ev_fork, cudaEventDisableTiming);
        cudaEventCreateWithFlags(&ev_join, cudaEventDisableTiming);
        cudaFuncSetAttribute(gemm_tc, cudaFuncAttributeMaxDynamicSharedMemorySize,
                             smem_bytes);
        cudaGetSymbolAddress(&p_cnt, g_cnt);
    }

    // Parallel section: hist+scan (~24us of work) vs gemm (now ~28us).
    cudaEventRecord(ev_fork, 0);
    cudaStreamWaitEvent(s_csr, ev_fork, 0);
    cudaMemsetAsync(p_cnt, 0, (size_t)n * sizeof(int), s_csr);
    hist_kernel<<<(E + 255) / 256, 256, 0, s_csr>>>(ei, E);
    scan1_kernel<<<nb, 256, 0, s_csr>>>(n);
    scan2_kernel<<<1, 128, 0, s_csr>>>(nb);
    cudaEventRecord(ev_join, s_csr);

    gemm_tc<<<(n + 127) / 128, 256, smem_bytes>>>(x, W, bproj, att_s, att_d, n);

    // fill runs alone on the full machine (after gemm AND the scan chain).
    cudaStreamWaitEvent(0, ev_join, 0);
    fill_kernel<<<(E + 255) / 256, 256>>>(ei, E);
    gather_kernel<<<(n + 1) / 2, 64>>>(bias, out, n);
}